// round 2
// baseline (speedup 1.0000x reference)
#include <cuda_runtime.h>
#include <cuda_bf16.h>
#include <cstdint>

// Problem constants
#define BATCH 16
#define CDIM 256          // embedding dim (channels)
#define HW 4096           // 64*64 pixels per image
#define NPIX 65536        // BATCH * HW
#define KCODES 1024
#define TILE_N 128        // pixels per CTA
#define TILE_K 128        // codes per k-tile
#define DCH 64            // d-chunk for codebook staging
#define NTILES 512        // NPIX / TILE_N

#define QOFF 0
#define LOSS_OFF 16777216        // 16*256*64*64
#define IDX_OFF  16777217

// scratch (no cudaMalloc allowed)
__device__ int    g_idx[NPIX];
__device__ float  g_s2[KCODES];
__device__ double g_partial[NTILES];

// ---------------------------------------------------------------------------
// Kernel 0: ||e||^2 per code
// ---------------------------------------------------------------------------
__global__ void k_s2(const float* __restrict__ cb, float* __restrict__ s2) {
    int k = blockIdx.x * blockDim.x + threadIdx.x;
    if (k < KCODES) {
        const float* row = cb + (size_t)k * CDIM;
        float s = 0.f;
        #pragma unroll 8
        for (int d = 0; d < CDIM; ++d) s += row[d] * row[d];
        s2[k] = s;
    }
}

// ---------------------------------------------------------------------------
// Kernel 1: distances GEMM + argmin.  256 threads, 1 CTA/SM.
// smem: xs[256][128] (128KB) + bs[64][128] (32KB) + s1[128]
// ---------------------------------------------------------------------------
__global__ void __launch_bounds__(256, 1)
k_argmin(const float* __restrict__ in, const float* __restrict__ cb,
         const float* __restrict__ s2g, int* __restrict__ gidx) {
    extern __shared__ float sm[];
    float* xs = sm;                       // 256*128 floats
    float* bs = sm + 256 * 128;           // 64*128 floats
    float* s1 = sm + 256 * 128 + 64 * 128;// 128 floats

    const int tid = threadIdx.x;
    const int blk = blockIdx.x;
    const int b   = blk >> 5;             // 32 tiles per image
    const int hw0 = (blk & 31) << 7;
    const float* inb = in + ((size_t)b << 20); // b * 256 * 4096

    // stage x tile: xs[d][p], coalesced float4 loads
    for (int t = tid; t < 256 * 32; t += 256) {
        int d  = t >> 5;
        int p4 = t & 31;
        float4 v = *(const float4*)(inb + (size_t)d * HW + hw0 + p4 * 4);
        *(float4*)(xs + d * TILE_N + p4 * 4) = v;
    }
    __syncthreads();

    // s1[p] = sum_d x^2 (sequential fp32)
    if (tid < TILE_N) {
        float s = 0.f;
        #pragma unroll 8
        for (int d = 0; d < CDIM; ++d) {
            float v = xs[d * TILE_N + tid];
            s += v * v;
        }
        s1[tid] = s;
    }
    __syncthreads();

    const int ty = tid >> 4;   // 0..15  (pixel groups)
    const int tx = tid & 15;   // 0..15  (code groups)

    float bestd[8];
    int   besti[8];
    float s1r[8];
    #pragma unroll
    for (int i = 0; i < 8; ++i) {
        bestd[i] = 3.4e38f;
        besti[i] = 0;
        int p = (i < 4) ? (ty * 4 + i) : (64 + ty * 4 + (i - 4));
        s1r[i] = s1[p];
    }

    for (int kt = 0; kt < KCODES / TILE_K; ++kt) {
        float mm[8][8];
        #pragma unroll
        for (int i = 0; i < 8; ++i)
            #pragma unroll
            for (int j = 0; j < 8; ++j) mm[i][j] = 0.f;

        for (int dc = 0; dc < CDIM / DCH; ++dc) {
            // stage bs[d_local][k_local] (transpose from row-major codebook)
            for (int t = tid; t < TILE_K * (DCH / 4); t += 256) {
                int kl = t & 127;
                int dq = t >> 7;   // 0..15, 4 d's each
                float4 v = *(const float4*)(cb + (size_t)(kt * TILE_K + kl) * CDIM
                                               + dc * DCH + dq * 4);
                bs[(dq * 4 + 0) * TILE_K + kl] = v.x;
                bs[(dq * 4 + 1) * TILE_K + kl] = v.y;
                bs[(dq * 4 + 2) * TILE_K + kl] = v.z;
                bs[(dq * 4 + 3) * TILE_K + kl] = v.w;
            }
            __syncthreads();

            const float* xbase = xs + (dc * DCH) * TILE_N;
            #pragma unroll 2
            for (int dl = 0; dl < DCH; ++dl) {
                const float* xr = xbase + dl * TILE_N;
                const float* br = bs + dl * TILE_K;
                float4 A0 = *(const float4*)(xr + (ty << 2));
                float4 A1 = *(const float4*)(xr + 64 + (ty << 2));
                float4 B0 = *(const float4*)(br + (tx << 2));
                float4 B1 = *(const float4*)(br + 64 + (tx << 2));
                float a[8]  = {A0.x, A0.y, A0.z, A0.w, A1.x, A1.y, A1.z, A1.w};
                float bb[8] = {B0.x, B0.y, B0.z, B0.w, B1.x, B1.y, B1.z, B1.w};
                #pragma unroll
                for (int i = 0; i < 8; ++i)
                    #pragma unroll
                    for (int j = 0; j < 8; ++j)
                        mm[i][j] = fmaf(a[i], bb[j], mm[i][j]);
            }
            __syncthreads();
        }

        // fold into distances; ascending code index within thread -> strict <
        // preserves first-occurrence tie-break.
        #pragma unroll
        for (int j = 0; j < 8; ++j) {
            int k = kt * TILE_K + ((j < 4) ? (tx * 4 + j) : (64 + tx * 4 + (j - 4)));
            float s2k = __ldg(&s2g[k]);
            #pragma unroll
            for (int i = 0; i < 8; ++i) {
                // matches ref rounding: fl( fl(s1+s2) - 2*mm ), 2*mm exact
                float dist = (s1r[i] + s2k) - 2.0f * mm[i][j];
                if (dist < bestd[i]) { bestd[i] = dist; besti[i] = k; }
            }
        }
    }

    // cross-thread (tx) reduction, lexicographic (dist, idx) min == jnp.argmin
    __syncthreads();
    float* rd = bs;                       // 128*16 floats
    int*   ri = (int*)(bs + TILE_N * 16); // 128*16 ints
    #pragma unroll
    for (int i = 0; i < 8; ++i) {
        int p = (i < 4) ? (ty * 4 + i) : (64 + ty * 4 + (i - 4));
        rd[p * 16 + tx] = bestd[i];
        ri[p * 16 + tx] = besti[i];
    }
    __syncthreads();
    if (tid < TILE_N) {
        float bd = rd[tid * 16];
        int   bi = ri[tid * 16];
        #pragma unroll
        for (int t = 1; t < 16; ++t) {
            float d = rd[tid * 16 + t];
            int   ii = ri[tid * 16 + t];
            if (d < bd || (d == bd && ii < bi)) { bd = d; bi = ii; }
        }
        gidx[(b << 12) + hw0 + tid] = bi;
    }
}

// ---------------------------------------------------------------------------
// Kernel 2: gather quantized output (coalesced writes), indices-as-float,
//           per-CTA loss partial in double.
// ---------------------------------------------------------------------------
__global__ void __launch_bounds__(256)
k_out(const float* __restrict__ in, const float* __restrict__ cb,
      const int* __restrict__ gidx, float* __restrict__ out,
      double* __restrict__ partial) {
    __shared__ int idxs[TILE_N];
    __shared__ double red[256];
    const int tid = threadIdx.x;
    const int blk = blockIdx.x;
    const int b   = blk >> 5;
    const int hw0 = (blk & 31) << 7;

    if (tid < TILE_N) {
        int v = gidx[(b << 12) + hw0 + tid];
        idxs[tid] = v;
        out[IDX_OFF + (b << 12) + hw0 + tid] = (float)v; // exact for idx<2^24
    }
    __syncthreads();

    const float* inb  = in  + ((size_t)b << 20);
    float*       outb = out + QOFF + ((size_t)b << 20);

    double acc = 0.0;
    // thread keeps fixed pixel p, walks d (good L1 reuse of its code row)
    for (int t = tid; t < CDIM * TILE_N; t += 256) {
        int d = t >> 7;
        int p = t & 127;
        float q = cb[(size_t)idxs[p] * CDIM + d];
        float x = inb[(size_t)d * HW + hw0 + p];
        outb[(size_t)d * HW + hw0 + p] = q;   // coalesced (p contiguous)
        float df = q - x;
        acc += (double)df * (double)df;
    }

    red[tid] = acc;
    __syncthreads();
    #pragma unroll
    for (int s = 128; s > 0; s >>= 1) {
        if (tid < s) red[tid] += red[tid + s];
        __syncthreads();
    }
    if (tid == 0) partial[blk] = red[0];
}

// ---------------------------------------------------------------------------
// Kernel 3: deterministic final loss reduction
// ---------------------------------------------------------------------------
__global__ void k_final(const double* __restrict__ partial, float* __restrict__ out) {
    __shared__ double red[256];
    int tid = threadIdx.x;
    double a = 0.0;
    for (int t = tid; t < NTILES; t += 256) a += partial[t];
    red[tid] = a;
    __syncthreads();
    #pragma unroll
    for (int s = 128; s > 0; s >>= 1) {
        if (tid < s) red[tid] += red[tid + s];
        __syncthreads();
    }
    if (tid == 0) {
        double mse = red[0] / (double)(NPIX * (double)CDIM);
        out[LOSS_OFF] = (float)(1.25 * mse);  // q_loss + 0.25 * e_loss
    }
}

// ---------------------------------------------------------------------------
extern "C" void kernel_launch(void* const* d_in, const int* in_sizes, int n_in,
                              void* d_out, int out_size) {
    (void)in_sizes; (void)n_in; (void)out_size;
    const float* in  = (const float*)d_in[0];
    const float* cb  = (const float*)d_in[1];
    float* out = (float*)d_out;

    int*    idx_p;
    float*  s2_p;
    double* part_p;
    cudaGetSymbolAddress((void**)&idx_p,  g_idx);
    cudaGetSymbolAddress((void**)&s2_p,   g_s2);
    cudaGetSymbolAddress((void**)&part_p, g_partial);

    const int smem1 = (256 * 128 + 64 * 128 + 128) * sizeof(float); // 164352
    cudaFuncSetAttribute(k_argmin, cudaFuncAttributeMaxDynamicSharedMemorySize, smem1);

    k_s2<<<(KCODES + 255) / 256, 256>>>(cb, s2_p);
    k_argmin<<<NTILES, 256, smem1>>>(in, cb, s2_p, idx_p);
    k_out<<<NTILES, 256>>>(in, cb, idx_p, out, part_p);
    k_final<<<1, 256>>>(part_p, out);
}

// round 4
// speedup vs baseline: 1.4422x; 1.4422x over previous
#include <cuda_runtime.h>
#include <cuda_fp16.h>
#include <cstdint>

#define CDIM 256
#define HW 4096
#define NPIX 65536
#define KCODES 1024
#define NTILES 512
#define LOSS_OFF 16777216
#define IDX_OFF  16777217

// scratch (__device__ globals; no cudaMalloc allowed)
__device__ __half  g_A[(size_t)NPIX * 512];     // [pixel][xh(256)|xl(256)]   64 MB
__device__ __half  g_B[(size_t)KCODES * 768];   // [code][Eh|Eh|El]           1.5 MB
__device__ float   g_s1[NPIX];
__device__ float   g_s2[KCODES];
__device__ int     g_idx[NPIX];
__device__ double  g_partial[NTILES];

__device__ __forceinline__ uint32_t smem_u32(const void* p) {
    uint32_t a;
    asm("{ .reg .u64 t; cvta.to.shared.u64 t, %1; cvt.u32.u64 %0, t; }" : "=r"(a) : "l"(p));
    return a;
}

#define LDSM4(r0, r1, r2, r3, addr) \
    asm volatile("ldmatrix.sync.aligned.m8n8.x4.shared.b16 {%0,%1,%2,%3}, [%4];" \
        : "=r"(r0), "=r"(r1), "=r"(r2), "=r"(r3) : "r"(addr))

#define MMA16816(c0, c1, c2, c3, a0, a1, a2, a3, b0, b1) \
    asm volatile("mma.sync.aligned.m16n8k16.row.col.f32.f16.f16.f32 " \
        "{%0,%1,%2,%3}, {%4,%5,%6,%7}, {%8,%9}, {%0,%1,%2,%3};" \
        : "+f"(c0), "+f"(c1), "+f"(c2), "+f"(c3) \
        : "r"(a0), "r"(a1), "r"(a2), "r"(a3), "r"(b0), "r"(b1))

// ---------------------------------------------------------------------------
// split codebook -> fp16 hi/lo (x1024) + ||e||^2
// ---------------------------------------------------------------------------
__global__ void k_split_b(const float* __restrict__ cb, __half* __restrict__ B_,
                          float* __restrict__ s2g) {
    int k = blockIdx.x * 256 + threadIdx.x;
    if (k >= KCODES) return;
    const float* row = cb + (size_t)k * CDIM;
    __half* o = B_ + (size_t)k * 768;
    float s = 0.f;
    for (int d = 0; d < CDIM; ++d) {
        float e = row[d];
        s += e * e;
        float E = e * 1024.0f;
        __half eh = __float2half_rn(E);
        __half el = __float2half_rn(E - __half2float(eh));
        o[d] = eh; o[256 + d] = eh; o[512 + d] = el;
    }
    s2g[k] = s;
}

// ---------------------------------------------------------------------------
// split inputs -> fp16 hi/lo, transposed to [pixel][d]; also s1 = ||x||^2
// ---------------------------------------------------------------------------
__global__ void __launch_bounds__(256, 1)
k_split_a(const float* __restrict__ in, __half* __restrict__ A_,
          float* __restrict__ s1g) {
    extern __shared__ float xs[];   // [256 d][stride 133]
    const int tid = threadIdx.x;
    const int blk = blockIdx.x;
    const int b = blk >> 5, hw0 = (blk & 31) << 7;
    const float* inb = in + ((size_t)b << 20);

    for (int t = tid; t < 256 * 32; t += 256) {
        int d = t >> 5, p4 = t & 31;
        float4 v = *(const float4*)(inb + (size_t)d * HW + hw0 + p4 * 4);
        float* dst = xs + d * 133 + p4 * 4;
        dst[0] = v.x; dst[1] = v.y; dst[2] = v.z; dst[3] = v.w;
    }
    __syncthreads();

    if (tid < 128) {
        float s = 0.f;
        for (int d = 0; d < CDIM; ++d) { float v = xs[d * 133 + tid]; s += v * v; }
        s1g[blk * 128 + tid] = s;
    }

    const int d = tid;   // each thread owns one channel; iterate pixels
    for (int i = 0; i < 128; ++i) {
        float x = xs[d * 133 + i];
        __half xh = __float2half_rn(x);
        __half xl = __float2half_rn(x - __half2float(xh));
        size_t row = ((size_t)(blk * 128 + i)) << 9;   // *512
        A_[row + d] = xh;
        A_[row + 256 + d] = xl;
    }
}

// ---------------------------------------------------------------------------
// HMMA GEMM + fused argmin
// smem: [0,4096) s2 (reused for final reduce) | [4096) 2 stages x (A 18432 + B 18432)
// A tile: 128 rows x 144B (128B data + 16 pad) ; B tile same.
// ---------------------------------------------------------------------------
__device__ __forceinline__ void load_chunk(uint32_t sb, const char* Ag, const char* Bg,
                                           int p0, int nt, int kc, int buf, int tid) {
    const uint32_t sA = sb + 4096 + buf * 36864;
    const uint32_t sB = sA + 18432;
    const size_t aoff = (size_t)(kc & 7) * 128;
    const size_t boff = (size_t)kc * 128;
    #pragma unroll
    for (int i = 0; i < 4; ++i) {
        int o = tid + 256 * i;           // 0..1023
        int row = o >> 3, seg = (o & 7) * 16;
        const char* src = Ag + ((size_t)(p0 + row) << 10) + aoff + seg;
        uint32_t dst = sA + row * 144 + seg;
        asm volatile("cp.async.cg.shared.global [%0], [%1], 16;" :: "r"(dst), "l"(src));
    }
    #pragma unroll
    for (int i = 0; i < 4; ++i) {
        int o = tid + 256 * i;
        int row = o >> 3, seg = (o & 7) * 16;
        const char* src = Bg + (size_t)(nt * 128 + row) * 1536 + boff + seg;
        uint32_t dst = sB + row * 144 + seg;
        asm volatile("cp.async.cg.shared.global [%0], [%1], 16;" :: "r"(dst), "l"(src));
    }
}

__global__ void __launch_bounds__(256, 2)
k_gemm(const __half* __restrict__ Ah, const __half* __restrict__ Bh,
       const float* __restrict__ s1g, const float* __restrict__ s2g,
       int* __restrict__ gidx) {
    extern __shared__ char sm[];
    float* s2s = (float*)sm;
    uint32_t sb = smem_u32(sm);
    const int tid = threadIdx.x, lane = tid & 31, wid = tid >> 5;
    const int warp_m = wid >> 1, warp_n = wid & 1;
    const int m0 = warp_m * 32, n0 = warp_n * 64;
    const int p0 = blockIdx.x * 128;
    const char* Ag = (const char*)Ah;
    const char* Bg = (const char*)Bh;

    for (int t = tid; t < KCODES; t += 256) s2s[t] = s2g[t];

    // per-thread ldmatrix address offsets (within a stage tile)
    const int rA = (lane & 7) + ((lane >> 3) & 1) * 8;    // 0..15
    const int cA = (lane >> 4) * 16;                      // 0 or 16 bytes (k8)
    const uint32_t aoff0 = (m0 + 0 + rA) * 144 + cA;
    const uint32_t aoff1 = (m0 + 16 + rA) * 144 + cA;
    const int rB = (lane & 7) + ((lane >> 4) << 3);       // 0..15
    const int cB = ((lane >> 3) & 1) * 16;                // 0 or 16 bytes (k8)
    uint32_t boff[4];
    #pragma unroll
    for (int nb = 0; nb < 4; ++nb) boff[nb] = (n0 + nb * 16 + rB) * 144 + cB;

    // s1 for the 4 row-slots this thread owns
    float s1v[4];
    #pragma unroll
    for (int s = 0; s < 4; ++s)
        s1v[s] = s1g[p0 + m0 + (s >> 1) * 16 + (lane >> 2) + (s & 1) * 8];

    float bd[4] = {3.4e38f, 3.4e38f, 3.4e38f, 3.4e38f};
    int   bi[4] = {0, 0, 0, 0};
    float c[2][8][4];

    // prologue
    load_chunk(sb, Ag, Bg, p0, 0, 0, 0, tid);
    asm volatile("cp.async.commit_group;" ::: "memory");

    const float SC = 0.001953125f;   // 2^-9

    for (int it = 0; it < 96; ++it) {
        const int nt = it / 12, kc = it - nt * 12, buf = it & 1;
        __syncthreads();             // all warps done with buf^1 from it-1
        if (it + 1 < 96) {
            const int it2 = it + 1, nt2 = it2 / 12, kc2 = it2 - nt2 * 12;
            load_chunk(sb, Ag, Bg, p0, nt2, kc2, buf ^ 1, tid);
            asm volatile("cp.async.commit_group;" ::: "memory");
            asm volatile("cp.async.wait_group 1;" ::: "memory");
        } else {
            asm volatile("cp.async.wait_group 0;" ::: "memory");
        }
        __syncthreads();             // chunk `it` data visible to all

        if (kc == 0) {
            #pragma unroll
            for (int mf = 0; mf < 2; ++mf)
                #pragma unroll
                for (int j = 0; j < 8; ++j)
                    #pragma unroll
                    for (int q = 0; q < 4; ++q) c[mf][j][q] = 0.f;
        }

        const uint32_t sA = sb + 4096 + buf * 36864;
        const uint32_t sB = sA + 18432;
        #pragma unroll
        for (int ks = 0; ks < 4; ++ks) {
            uint32_t a0[4], a1[4], bf0[4], bf1[4], bf2[4], bf3[4];
            LDSM4(a0[0], a0[1], a0[2], a0[3], sA + aoff0 + ks * 32);
            LDSM4(a1[0], a1[1], a1[2], a1[3], sA + aoff1 + ks * 32);
            LDSM4(bf0[0], bf0[1], bf0[2], bf0[3], sB + boff[0] + ks * 32);
            LDSM4(bf1[0], bf1[1], bf1[2], bf1[3], sB + boff[1] + ks * 32);
            LDSM4(bf2[0], bf2[1], bf2[2], bf2[3], sB + boff[2] + ks * 32);
            LDSM4(bf3[0], bf3[1], bf3[2], bf3[3], sB + boff[3] + ks * 32);

            MMA16816(c[0][0][0], c[0][0][1], c[0][0][2], c[0][0][3],
                     a0[0], a0[1], a0[2], a0[3], bf0[0], bf0[1]);
            MMA16816(c[0][1][0], c[0][1][1], c[0][1][2], c[0][1][3],
                     a0[0], a0[1], a0[2], a0[3], bf0[2], bf0[3]);
            MMA16816(c[0][2][0], c[0][2][1], c[0][2][2], c[0][2][3],
                     a0[0], a0[1], a0[2], a0[3], bf1[0], bf1[1]);
            MMA16816(c[0][3][0], c[0][3][1], c[0][3][2], c[0][3][3],
                     a0[0], a0[1], a0[2], a0[3], bf1[2], bf1[3]);
            MMA16816(c[0][4][0], c[0][4][1], c[0][4][2], c[0][4][3],
                     a0[0], a0[1], a0[2], a0[3], bf2[0], bf2[1]);
            MMA16816(c[0][5][0], c[0][5][1], c[0][5][2], c[0][5][3],
                     a0[0], a0[1], a0[2], a0[3], bf2[2], bf2[3]);
            MMA16816(c[0][6][0], c[0][6][1], c[0][6][2], c[0][6][3],
                     a0[0], a0[1], a0[2], a0[3], bf3[0], bf3[1]);
            MMA16816(c[0][7][0], c[0][7][1], c[0][7][2], c[0][7][3],
                     a0[0], a0[1], a0[2], a0[3], bf3[2], bf3[3]);

            MMA16816(c[1][0][0], c[1][0][1], c[1][0][2], c[1][0][3],
                     a1[0], a1[1], a1[2], a1[3], bf0[0], bf0[1]);
            MMA16816(c[1][1][0], c[1][1][1], c[1][1][2], c[1][1][3],
                     a1[0], a1[1], a1[2], a1[3], bf0[2], bf0[3]);
            MMA16816(c[1][2][0], c[1][2][1], c[1][2][2], c[1][2][3],
                     a1[0], a1[1], a1[2], a1[3], bf1[0], bf1[1]);
            MMA16816(c[1][3][0], c[1][3][1], c[1][3][2], c[1][3][3],
                     a1[0], a1[1], a1[2], a1[3], bf1[2], bf1[3]);
            MMA16816(c[1][4][0], c[1][4][1], c[1][4][2], c[1][4][3],
                     a1[0], a1[1], a1[2], a1[3], bf2[0], bf2[1]);
            MMA16816(c[1][5][0], c[1][5][1], c[1][5][2], c[1][5][3],
                     a1[0], a1[1], a1[2], a1[3], bf2[2], bf2[3]);
            MMA16816(c[1][6][0], c[1][6][1], c[1][6][2], c[1][6][3],
                     a1[0], a1[1], a1[2], a1[3], bf3[0], bf3[1]);
            MMA16816(c[1][7][0], c[1][7][1], c[1][7][2], c[1][7][3],
                     a1[0], a1[1], a1[2], a1[3], bf3[2], bf3[3]);
        }

        if (kc == 11) {
            // fold this N-tile into running argmin (ascending n within thread)
            #pragma unroll
            for (int mf = 0; mf < 2; ++mf) {
                #pragma unroll
                for (int j = 0; j < 8; ++j) {
                    const int nb = nt * 128 + n0 + j * 8 + ((lane & 3) << 1);
                    const float s2a = s2s[nb], s2b = s2s[nb + 1];
                    const int sl0 = mf * 2, sl1 = mf * 2 + 1;
                    float d0 = (s1v[sl0] + s2a) - c[mf][j][0] * SC;
                    float d1 = (s1v[sl0] + s2b) - c[mf][j][1] * SC;
                    float d2 = (s1v[sl1] + s2a) - c[mf][j][2] * SC;
                    float d3 = (s1v[sl1] + s2b) - c[mf][j][3] * SC;
                    if (d0 < bd[sl0]) { bd[sl0] = d0; bi[sl0] = nb; }
                    if (d1 < bd[sl0]) { bd[sl0] = d1; bi[sl0] = nb + 1; }
                    if (d2 < bd[sl1]) { bd[sl1] = d2; bi[sl1] = nb; }
                    if (d3 < bd[sl1]) { bd[sl1] = d3; bi[sl1] = nb + 1; }
                }
            }
        }
    }

    // quad reduce (lanes sharing a row differ only in lane&3), lexicographic
    #pragma unroll
    for (int s = 0; s < 4; ++s) {
        #pragma unroll
        for (int off = 1; off <= 2; off <<= 1) {
            float od = __shfl_xor_sync(0xffffffffu, bd[s], off);
            int   oi = __shfl_xor_sync(0xffffffffu, bi[s], off);
            if (od < bd[s] || (od == bd[s] && oi < bi[s])) { bd[s] = od; bi[s] = oi; }
        }
    }
    __syncthreads();
    float* rd = (float*)sm;             // reuse s2 region
    int*   ri = (int*)(sm + 1024);
    if ((lane & 3) == 0) {
        #pragma unroll
        for (int s = 0; s < 4; ++s) {
            int row = m0 + (s >> 1) * 16 + (lane >> 2) + (s & 1) * 8;
            rd[row * 2 + warp_n] = bd[s];
            ri[row * 2 + warp_n] = bi[s];
        }
    }
    __syncthreads();
    if (tid < 128) {
        float d0 = rd[tid * 2], d1 = rd[tid * 2 + 1];
        int i0 = ri[tid * 2], i1 = ri[tid * 2 + 1];
        gidx[p0 + tid] = (d1 < d0 || (d1 == d0 && i1 < i0)) ? i1 : i0;
    }
}

// ---------------------------------------------------------------------------
// gather quantized output + indices-as-float + loss partials (double)
// ---------------------------------------------------------------------------
__global__ void __launch_bounds__(256)
k_out(const float* __restrict__ in, const float* __restrict__ cb,
      const int* __restrict__ gidx, float* __restrict__ out,
      double* __restrict__ partial) {
    __shared__ int idxs[128];
    __shared__ double red[256];
    const int tid = threadIdx.x;
    const int blk = blockIdx.x;
    const int b = blk >> 5, hw0 = (blk & 31) << 7;

    if (tid < 128) {
        int v = gidx[(b << 12) + hw0 + tid];
        idxs[tid] = v;
        out[IDX_OFF + (b << 12) + hw0 + tid] = (float)v;
    }
    __syncthreads();

    const float* inb  = in  + ((size_t)b << 20);
    float*       outb = out + ((size_t)b << 20);

    double acc = 0.0;
    for (int t = tid; t < CDIM * 128; t += 256) {
        int d = t >> 7, p = t & 127;
        float q = cb[(size_t)idxs[p] * CDIM + d];
        float x = inb[(size_t)d * HW + hw0 + p];
        outb[(size_t)d * HW + hw0 + p] = q;
        float df = q - x;
        acc += (double)df * (double)df;
    }

    red[tid] = acc;
    __syncthreads();
    #pragma unroll
    for (int s = 128; s > 0; s >>= 1) {
        if (tid < s) red[tid] += red[tid + s];
        __syncthreads();
    }
    if (tid == 0) partial[blk] = red[0];
}

__global__ void k_final(const double* __restrict__ partial, float* __restrict__ out) {
    __shared__ double red[256];
    int tid = threadIdx.x;
    double a = 0.0;
    for (int t = tid; t < NTILES; t += 256) a += partial[t];
    red[tid] = a;
    __syncthreads();
    #pragma unroll
    for (int s = 128; s > 0; s >>= 1) {
        if (tid < s) red[tid] += red[tid + s];
        __syncthreads();
    }
    if (tid == 0) {
        double mse = red[0] / (double)(NPIX * (double)CDIM);
        out[LOSS_OFF] = (float)(1.25 * mse);
    }
}

// ---------------------------------------------------------------------------
extern "C" void kernel_launch(void* const* d_in, const int* in_sizes, int n_in,
                              void* d_out, int out_size) {
    (void)in_sizes; (void)n_in; (void)out_size;
    const float* in = (const float*)d_in[0];
    const float* cb = (const float*)d_in[1];
    float* out = (float*)d_out;

    __half* A_p; __half* B_p;
    float *s1_p, *s2_p; int* idx_p; double* part_p;
    cudaGetSymbolAddress((void**)&A_p,   g_A);
    cudaGetSymbolAddress((void**)&B_p,   g_B);
    cudaGetSymbolAddress((void**)&s1_p,  g_s1);
    cudaGetSymbolAddress((void**)&s2_p,  g_s2);
    cudaGetSymbolAddress((void**)&idx_p, g_idx);
    cudaGetSymbolAddress((void**)&part_p, g_partial);

    const int smem_a = 256 * 133 * 4;            // 136192
    const int smem_g = 4096 + 2 * 36864;         // 77824
    cudaFuncSetAttribute(k_split_a, cudaFuncAttributeMaxDynamicSharedMemorySize, smem_a);
    cudaFuncSetAttribute(k_gemm,    cudaFuncAttributeMaxDynamicSharedMemorySize, smem_g);

    k_split_b<<<4, 256>>>(cb, B_p, s2_p);
    k_split_a<<<NTILES, 256, smem_a>>>(in, A_p, s1_p);
    k_gemm<<<NTILES, 256, smem_g>>>(A_p, B_p, s1_p, s2_p, idx_p);
    k_out<<<NTILES, 256>>>(in, cb, idx_p, out, part_p);
    k_final<<<1, 256>>>(part_p, out);
}

// round 7
// speedup vs baseline: 1.5081x; 1.0457x over previous
#include <cuda_runtime.h>
#include <cuda_fp16.h>
#include <cstdint>

#define CDIM 256
#define HW 4096
#define NPIX 65536
#define KCODES 1024
#define NTILES 512
#define LOSS_OFF 16777216
#define IDX_OFF  16777217

// scratch (__device__ globals; no cudaMalloc allowed)
__device__ __half  g_A[(size_t)NPIX * 512];     // [pixel][xh(256)|xl(256)]   64 MB
__device__ __half  g_B[(size_t)KCODES * 768];   // [code][Eh|Eh|El]           1.5 MB
__device__ float   g_s1[NPIX];
__device__ float   g_s2[KCODES];
__device__ float   g_cand_d[NPIX * 8];
__device__ int     g_cand_i[NPIX * 8];
__device__ double  g_partial[NTILES];

__device__ __forceinline__ uint32_t smem_u32(const void* p) {
    uint32_t a;
    asm("{ .reg .u64 t; cvta.to.shared.u64 t, %1; cvt.u32.u64 %0, t; }" : "=r"(a) : "l"(p));
    return a;
}

#define LDSM4(r0, r1, r2, r3, addr) \
    asm volatile("ldmatrix.sync.aligned.m8n8.x4.shared.b16 {%0,%1,%2,%3}, [%4];" \
        : "=r"(r0), "=r"(r1), "=r"(r2), "=r"(r3) : "r"(addr))

#define MMA16816(c0, c1, c2, c3, a0, a1, a2, a3, b0, b1) \
    asm volatile("mma.sync.aligned.m16n8k16.row.col.f32.f16.f16.f32 " \
        "{%0,%1,%2,%3}, {%4,%5,%6,%7}, {%8,%9}, {%0,%1,%2,%3};" \
        : "+f"(c0), "+f"(c1), "+f"(c2), "+f"(c3) \
        : "r"(a0), "r"(a1), "r"(a2), "r"(a3), "r"(b0), "r"(b1))

// ---------------------------------------------------------------------------
// split codebook -> fp16 hi/lo (x1024) + ||e||^2   (proven R4)
// ---------------------------------------------------------------------------
__global__ void k_split_b(const float* __restrict__ cb, __half* __restrict__ B_,
                          float* __restrict__ s2g) {
    int k = blockIdx.x * 256 + threadIdx.x;
    if (k >= KCODES) return;
    const float* row = cb + (size_t)k * CDIM;
    __half* o = B_ + (size_t)k * 768;
    float s = 0.f;
    for (int d = 0; d < CDIM; ++d) {
        float e = row[d];
        s += e * e;
        float E = e * 1024.0f;
        __half eh = __float2half_rn(E);
        __half el = __float2half_rn(E - __half2float(eh));
        o[d] = eh; o[256 + d] = eh; o[512 + d] = el;
    }
    s2g[k] = s;
}

// ---------------------------------------------------------------------------
// split inputs -> fp16 hi/lo, [pixel][d]; s1 sequential-d   (proven R4)
// ---------------------------------------------------------------------------
__global__ void __launch_bounds__(256, 1)
k_split_a(const float* __restrict__ in, __half* __restrict__ A_,
          float* __restrict__ s1g) {
    extern __shared__ float xs[];   // [256 d][stride 133]
    const int tid = threadIdx.x;
    const int blk = blockIdx.x;
    const int b = blk >> 5, hw0 = (blk & 31) << 7;
    const float* inb = in + ((size_t)b << 20);

    for (int t = tid; t < 8192; t += 256) {
        int d = t >> 5, p4 = t & 31;
        float4 v = *(const float4*)(inb + (size_t)d * HW + hw0 + p4 * 4);
        float* dst = xs + d * 133 + p4 * 4;
        dst[0] = v.x; dst[1] = v.y; dst[2] = v.z; dst[3] = v.w;
    }
    __syncthreads();

    if (tid < 128) {
        float s = 0.f;
        for (int d = 0; d < CDIM; ++d) { float v = xs[d * 133 + tid]; s += v * v; }
        s1g[blk * 128 + tid] = s;
    }

    const int d = tid;   // each thread owns one channel; iterate pixels
    for (int i = 0; i < 128; ++i) {
        float x = xs[d * 133 + i];
        __half xh = __float2half_rn(x);
        __half xl = __float2half_rn(x - __half2float(xh));
        size_t row = ((size_t)(blk * 128 + i)) << 9;   // *512
        A_[row + d] = xh;
        A_[row + 256 + d] = xl;
    }
}

// ---------------------------------------------------------------------------
// HMMA GEMM tile: 128 pixels x 128 codes. nt = blk&7 selects one of EIGHT
// 128-code tiles (8*128 = 1024 = KCODES).  Inner body: proven R4 code.
// smem: [0,1KB) rd | [1KB,2KB) ri | [2KB,2.5KB) s2 tile | [4KB) 2 x 36864 stages
// ---------------------------------------------------------------------------
__device__ __forceinline__ void load_chunk(uint32_t sb, const char* Ag, const char* Bg,
                                           int p0, int nt, int kc, int buf, int tid) {
    const uint32_t sA = sb + 4096 + buf * 36864;
    const uint32_t sB = sA + 18432;
    const size_t aoff = (size_t)(kc & 7) * 128;
    const size_t boff = (size_t)kc * 128;
    #pragma unroll
    for (int i = 0; i < 4; ++i) {
        int o = tid + 256 * i;           // 0..1023
        int row = o >> 3, seg = (o & 7) * 16;
        const char* src = Ag + ((size_t)(p0 + row) << 10) + aoff + seg;
        uint32_t dst = sA + row * 144 + seg;
        asm volatile("cp.async.cg.shared.global [%0], [%1], 16;" :: "r"(dst), "l"(src));
    }
    #pragma unroll
    for (int i = 0; i < 4; ++i) {
        int o = tid + 256 * i;
        int row = o >> 3, seg = (o & 7) * 16;
        const char* src = Bg + (size_t)(nt * 128 + row) * 1536 + boff + seg;
        uint32_t dst = sB + row * 144 + seg;
        asm volatile("cp.async.cg.shared.global [%0], [%1], 16;" :: "r"(dst), "l"(src));
    }
}

__global__ void __launch_bounds__(256, 2)
k_gemm(const __half* __restrict__ Ah, const __half* __restrict__ Bh,
       const float* __restrict__ s1g, const float* __restrict__ s2g,
       float* __restrict__ cand_d, int* __restrict__ cand_i) {
    extern __shared__ char sm[];
    uint32_t sb = smem_u32(sm);
    float* rd = (float*)sm;
    int*   ri = (int*)(sm + 1024);
    float* s2s = (float*)(sm + 2048);

    const int tid = threadIdx.x, lane = tid & 31, wid = tid >> 5;
    const int warp_m = wid >> 1, warp_n = wid & 1;
    const int m0 = warp_m * 32, n0 = warp_n * 64;
    const int blk = blockIdx.x, pb = blk >> 3, nt = blk & 7;   // EIGHT code tiles
    const int p0 = pb * 128;
    const char* Ag = (const char*)Ah;
    const char* Bg = (const char*)Bh;

    if (tid < 128) s2s[tid] = s2g[nt * 128 + tid];

    // per-thread ldmatrix address offsets (within a stage tile) — R4 proven
    const int rA = (lane & 7) + ((lane >> 3) & 1) * 8;    // 0..15
    const int cA = (lane >> 4) * 16;                      // 0 or 16 bytes (k8)
    const uint32_t aoff0 = (m0 + 0 + rA) * 144 + cA;
    const uint32_t aoff1 = (m0 + 16 + rA) * 144 + cA;
    const int rB = (lane & 7) + ((lane >> 4) << 3);       // 0..15
    const int cB = ((lane >> 3) & 1) * 16;                // 0 or 16 bytes (k8)
    uint32_t boff[4];
    #pragma unroll
    for (int nb = 0; nb < 4; ++nb) boff[nb] = (n0 + nb * 16 + rB) * 144 + cB;

    float s1v[4];
    #pragma unroll
    for (int s = 0; s < 4; ++s)
        s1v[s] = s1g[p0 + m0 + (s >> 1) * 16 + (lane >> 2) + (s & 1) * 8];

    float c[2][8][4];
    #pragma unroll
    for (int mf = 0; mf < 2; ++mf)
        #pragma unroll
        for (int j = 0; j < 8; ++j)
            #pragma unroll
            for (int q = 0; q < 4; ++q) c[mf][j][q] = 0.f;

    // prologue (R4 pattern)
    load_chunk(sb, Ag, Bg, p0, nt, 0, 0, tid);
    asm volatile("cp.async.commit_group;" ::: "memory");

    for (int kc = 0; kc < 12; ++kc) {
        const int buf = kc & 1;
        __syncthreads();             // all warps done with buf^1 from kc-1
        if (kc + 1 < 12) {
            load_chunk(sb, Ag, Bg, p0, nt, kc + 1, buf ^ 1, tid);
            asm volatile("cp.async.commit_group;" ::: "memory");
            asm volatile("cp.async.wait_group 1;" ::: "memory");
        } else {
            asm volatile("cp.async.wait_group 0;" ::: "memory");
        }
        __syncthreads();             // chunk `kc` data visible to all

        const uint32_t sA = sb + 4096 + buf * 36864;
        const uint32_t sB = sA + 18432;
        #pragma unroll
        for (int ks = 0; ks < 4; ++ks) {
            uint32_t a0[4], a1[4], bf0[4], bf1[4], bf2[4], bf3[4];
            LDSM4(a0[0], a0[1], a0[2], a0[3], sA + aoff0 + ks * 32);
            LDSM4(a1[0], a1[1], a1[2], a1[3], sA + aoff1 + ks * 32);
            LDSM4(bf0[0], bf0[1], bf0[2], bf0[3], sB + boff[0] + ks * 32);
            LDSM4(bf1[0], bf1[1], bf1[2], bf1[3], sB + boff[1] + ks * 32);
            LDSM4(bf2[0], bf2[1], bf2[2], bf2[3], sB + boff[2] + ks * 32);
            LDSM4(bf3[0], bf3[1], bf3[2], bf3[3], sB + boff[3] + ks * 32);

            MMA16816(c[0][0][0], c[0][0][1], c[0][0][2], c[0][0][3],
                     a0[0], a0[1], a0[2], a0[3], bf0[0], bf0[1]);
            MMA16816(c[0][1][0], c[0][1][1], c[0][1][2], c[0][1][3],
                     a0[0], a0[1], a0[2], a0[3], bf0[2], bf0[3]);
            MMA16816(c[0][2][0], c[0][2][1], c[0][2][2], c[0][2][3],
                     a0[0], a0[1], a0[2], a0[3], bf1[0], bf1[1]);
            MMA16816(c[0][3][0], c[0][3][1], c[0][3][2], c[0][3][3],
                     a0[0], a0[1], a0[2], a0[3], bf1[2], bf1[3]);
            MMA16816(c[0][4][0], c[0][4][1], c[0][4][2], c[0][4][3],
                     a0[0], a0[1], a0[2], a0[3], bf2[0], bf2[1]);
            MMA16816(c[0][5][0], c[0][5][1], c[0][5][2], c[0][5][3],
                     a0[0], a0[1], a0[2], a0[3], bf2[2], bf2[3]);
            MMA16816(c[0][6][0], c[0][6][1], c[0][6][2], c[0][6][3],
                     a0[0], a0[1], a0[2], a0[3], bf3[0], bf3[1]);
            MMA16816(c[0][7][0], c[0][7][1], c[0][7][2], c[0][7][3],
                     a0[0], a0[1], a0[2], a0[3], bf3[2], bf3[3]);

            MMA16816(c[1][0][0], c[1][0][1], c[1][0][2], c[1][0][3],
                     a1[0], a1[1], a1[2], a1[3], bf0[0], bf0[1]);
            MMA16816(c[1][1][0], c[1][1][1], c[1][1][2], c[1][1][3],
                     a1[0], a1[1], a1[2], a1[3], bf0[2], bf0[3]);
            MMA16816(c[1][2][0], c[1][2][1], c[1][2][2], c[1][2][3],
                     a1[0], a1[1], a1[2], a1[3], bf1[0], bf1[1]);
            MMA16816(c[1][3][0], c[1][3][1], c[1][3][2], c[1][3][3],
                     a1[0], a1[1], a1[2], a1[3], bf1[2], bf1[3]);
            MMA16816(c[1][4][0], c[1][4][1], c[1][4][2], c[1][4][3],
                     a1[0], a1[1], a1[2], a1[3], bf2[0], bf2[1]);
            MMA16816(c[1][5][0], c[1][5][1], c[1][5][2], c[1][5][3],
                     a1[0], a1[1], a1[2], a1[3], bf2[2], bf2[3]);
            MMA16816(c[1][6][0], c[1][6][1], c[1][6][2], c[1][6][3],
                     a1[0], a1[1], a1[2], a1[3], bf3[0], bf3[1]);
            MMA16816(c[1][7][0], c[1][7][1], c[1][7][2], c[1][7][3],
                     a1[0], a1[1], a1[2], a1[3], bf3[2], bf3[3]);
        }
    }

    // fold into per-thread argmin (ascending local n -> first-index tie-break)
    const float SC = 0.001953125f;   // 2^-9
    float bd[4] = {3.4e38f, 3.4e38f, 3.4e38f, 3.4e38f};
    int   bi[4] = {0, 0, 0, 0};
    #pragma unroll
    for (int mf = 0; mf < 2; ++mf) {
        #pragma unroll
        for (int j = 0; j < 8; ++j) {
            const int nl = n0 + j * 8 + ((lane & 3) << 1);
            const float s2a = s2s[nl], s2b = s2s[nl + 1];
            const int sl0 = mf * 2, sl1 = mf * 2 + 1;
            float d0 = (s1v[sl0] + s2a) - c[mf][j][0] * SC;
            float d1 = (s1v[sl0] + s2b) - c[mf][j][1] * SC;
            float d2 = (s1v[sl1] + s2a) - c[mf][j][2] * SC;
            float d3 = (s1v[sl1] + s2b) - c[mf][j][3] * SC;
            if (d0 < bd[sl0]) { bd[sl0] = d0; bi[sl0] = nl; }
            if (d1 < bd[sl0]) { bd[sl0] = d1; bi[sl0] = nl + 1; }
            if (d2 < bd[sl1]) { bd[sl1] = d2; bi[sl1] = nl; }
            if (d3 < bd[sl1]) { bd[sl1] = d3; bi[sl1] = nl + 1; }
        }
    }
    // quad reduce (lexicographic)
    #pragma unroll
    for (int s = 0; s < 4; ++s) {
        #pragma unroll
        for (int off = 1; off <= 2; off <<= 1) {
            float od = __shfl_xor_sync(0xffffffffu, bd[s], off);
            int   oi = __shfl_xor_sync(0xffffffffu, bi[s], off);
            if (od < bd[s] || (od == bd[s] && oi < bi[s])) { bd[s] = od; bi[s] = oi; }
        }
    }
    __syncthreads();
    if ((lane & 3) == 0) {
        #pragma unroll
        for (int s = 0; s < 4; ++s) {
            int row = m0 + (s >> 1) * 16 + (lane >> 2) + (s & 1) * 8;
            rd[row * 2 + warp_n] = bd[s];
            ri[row * 2 + warp_n] = bi[s];
        }
    }
    __syncthreads();
    if (tid < 128) {
        float d0 = rd[tid * 2], d1 = rd[tid * 2 + 1];
        int i0 = ri[tid * 2], i1 = ri[tid * 2 + 1];
        bool t1 = (d1 < d0 || (d1 == d0 && i1 < i0));
        cand_d[(size_t)(p0 + tid) * 8 + nt] = t1 ? d1 : d0;
        cand_i[(size_t)(p0 + tid) * 8 + nt] = nt * 128 + (t1 ? i1 : i0);
    }
}

// ---------------------------------------------------------------------------
// combine 8 candidates + coalesced gather (warp-per-pixel + smem transpose)
// smem: idxs[128] @0 | red[256] dbl @512 | qs[128][132] fp32 @2560
// ---------------------------------------------------------------------------
__global__ void __launch_bounds__(256)
k_out(const float* __restrict__ in, const float* __restrict__ cb,
      const float* __restrict__ cand_d, const int* __restrict__ cand_i,
      float* __restrict__ out, double* __restrict__ partial) {
    extern __shared__ char smo[];
    int* idxs = (int*)smo;
    double* red = (double*)(smo + 512);
    float* qs = (float*)(smo + 2560);
    const int tid = threadIdx.x;
    const int blk = blockIdx.x;
    const int b = blk >> 5, hw0 = (blk & 31) << 7;

    if (tid < 128) {
        size_t base = (size_t)((b << 12) + hw0 + tid) * 8;
        float bdv = cand_d[base]; int biv = cand_i[base];
        #pragma unroll
        for (int t = 1; t < 8; ++t) {
            float d = cand_d[base + t]; int i = cand_i[base + t];
            if (d < bdv || (d == bdv && i < biv)) { bdv = d; biv = i; }
        }
        idxs[tid] = biv;
        out[IDX_OFF + (b << 12) + hw0 + tid] = (float)biv;
    }
    __syncthreads();

    const float* inb  = in  + ((size_t)b << 20);
    float*       outb = out + ((size_t)b << 20);
    const int w = tid >> 5, l = tid & 31;
    double acc = 0.0;

    #pragma unroll
    for (int h = 0; h < 2; ++h) {
        for (int r = 0; r < 16; ++r) {
            int p = w * 16 + r;
            float4 q4 = *(const float4*)(cb + (size_t)idxs[p] * CDIM + h * 128 + l * 4);
            *(float4*)(qs + p * 132 + l * 4) = q4;
        }
        __syncthreads();
        for (int t = tid; t < 128 * 128; t += 256) {
            int dl = t >> 7, p = t & 127, d = h * 128 + dl;
            float q = qs[p * 132 + dl];
            float x = inb[(size_t)d * HW + hw0 + p];
            outb[(size_t)d * HW + hw0 + p] = q;
            float df = q - x;
            acc += (double)df * (double)df;
        }
        __syncthreads();
    }

    red[tid] = acc;
    __syncthreads();
    #pragma unroll
    for (int s = 128; s > 0; s >>= 1) {
        if (tid < s) red[tid] += red[tid + s];
        __syncthreads();
    }
    if (tid == 0) partial[blk] = red[0];
}

__global__ void k_final(const double* __restrict__ partial, float* __restrict__ out) {
    __shared__ double red[256];
    int tid = threadIdx.x;
    double a = 0.0;
    for (int t = tid; t < NTILES; t += 256) a += partial[t];
    red[tid] = a;
    __syncthreads();
    #pragma unroll
    for (int s = 128; s > 0; s >>= 1) {
        if (tid < s) red[tid] += red[tid + s];
        __syncthreads();
    }
    if (tid == 0) {
        double mse = red[0] / (double)(NPIX * (double)CDIM);
        out[LOSS_OFF] = (float)(1.25 * mse);
    }
}

// ---------------------------------------------------------------------------
extern "C" void kernel_launch(void* const* d_in, const int* in_sizes, int n_in,
                              void* d_out, int out_size) {
    (void)in_sizes; (void)n_in; (void)out_size;
    const float* in = (const float*)d_in[0];
    const float* cb = (const float*)d_in[1];
    float* out = (float*)d_out;

    __half* A_p; __half* B_p;
    float *s1_p, *s2_p, *cd_p; int* ci_p; double* part_p;
    cudaGetSymbolAddress((void**)&A_p,   g_A);
    cudaGetSymbolAddress((void**)&B_p,   g_B);
    cudaGetSymbolAddress((void**)&s1_p,  g_s1);
    cudaGetSymbolAddress((void**)&s2_p,  g_s2);
    cudaGetSymbolAddress((void**)&cd_p,  g_cand_d);
    cudaGetSymbolAddress((void**)&ci_p,  g_cand_i);
    cudaGetSymbolAddress((void**)&part_p, g_partial);

    const int smem_a = 256 * 133 * 4;            // 136192
    const int smem_g = 4096 + 2 * 36864;         // 77824 (same as proven R4)
    const int smem_o = 2560 + 128 * 132 * 4;     // 70144
    cudaFuncSetAttribute(k_split_a, cudaFuncAttributeMaxDynamicSharedMemorySize, smem_a);
    cudaFuncSetAttribute(k_gemm,    cudaFuncAttributeMaxDynamicSharedMemorySize, smem_g);
    cudaFuncSetAttribute(k_out,     cudaFuncAttributeMaxDynamicSharedMemorySize, smem_o);

    k_split_b<<<4, 256>>>(cb, B_p, s2_p);
    k_split_a<<<NTILES, 256, smem_a>>>(in, A_p, s1_p);
    k_gemm<<<4096, 256, smem_g>>>(A_p, B_p, s1_p, s2_p, cd_p, ci_p);
    k_out<<<NTILES, 256, smem_o>>>(in, cb, cd_p, ci_p, out, part_p);
    k_final<<<1, 256>>>(part_p, out);
}

// round 8
// speedup vs baseline: 1.5850x; 1.0510x over previous
#include <cuda_runtime.h>
#include <cuda_fp16.h>
#include <cstdint>

#define CDIM 256
#define HW 4096
#define NPIX 65536
#define KCODES 1024
#define NTILES 512
#define LOSS_OFF 16777216
#define IDX_OFF  16777217

// scratch (__device__ globals; no cudaMalloc allowed)
__device__ __half  g_A[(size_t)NPIX * 512];     // [pixel][xh(256)|xl(256)]   64 MB
__device__ __half  g_B[(size_t)KCODES * 768];   // [code][Eh|Eh|El]           1.5 MB
__device__ float   g_s1[NPIX];
__device__ float   g_s2[KCODES];
__device__ float   g_cand_d[NPIX * 8];
__device__ int     g_cand_i[NPIX * 8];
__device__ int     g_idx[NPIX];
__device__ double  g_partial[NTILES];

__device__ __forceinline__ uint32_t smem_u32(const void* p) {
    uint32_t a;
    asm("{ .reg .u64 t; cvta.to.shared.u64 t, %1; cvt.u32.u64 %0, t; }" : "=r"(a) : "l"(p));
    return a;
}

#define LDSM4(r0, r1, r2, r3, addr) \
    asm volatile("ldmatrix.sync.aligned.m8n8.x4.shared.b16 {%0,%1,%2,%3}, [%4];" \
        : "=r"(r0), "=r"(r1), "=r"(r2), "=r"(r3) : "r"(addr))

#define MMA16816(c0, c1, c2, c3, a0, a1, a2, a3, b0, b1) \
    asm volatile("mma.sync.aligned.m16n8k16.row.col.f32.f16.f16.f32 " \
        "{%0,%1,%2,%3}, {%4,%5,%6,%7}, {%8,%9}, {%0,%1,%2,%3};" \
        : "+f"(c0), "+f"(c1), "+f"(c2), "+f"(c3) \
        : "r"(a0), "r"(a1), "r"(a2), "r"(a3), "r"(b0), "r"(b1))

// ---------------------------------------------------------------------------
// split codebook -> fp16 hi/lo (x1024) + ||e||^2   (proven)
// ---------------------------------------------------------------------------
__global__ void k_split_b(const float* __restrict__ cb, __half* __restrict__ B_,
                          float* __restrict__ s2g) {
    int k = blockIdx.x * 256 + threadIdx.x;
    if (k >= KCODES) return;
    const float* row = cb + (size_t)k * CDIM;
    __half* o = B_ + (size_t)k * 768;
    float s = 0.f;
    for (int d = 0; d < CDIM; ++d) {
        float e = row[d];
        s += e * e;
        float E = e * 1024.0f;
        __half eh = __float2half_rn(E);
        __half el = __float2half_rn(E - __half2float(eh));
        o[d] = eh; o[256 + d] = eh; o[512 + d] = el;
    }
    s2g[k] = s;
}

// ---------------------------------------------------------------------------
// split inputs -> fp16 hi/lo [pixel][d]; s1 sequential-d (bit-identical order).
// Re-tiled to 64 px/CTA: smem 256x69 fp32 = 70.7KB -> 3 CTAs/SM.
// ---------------------------------------------------------------------------
__global__ void __launch_bounds__(256)
k_split_a(const float* __restrict__ in, __half* __restrict__ A_,
          float* __restrict__ s1g) {
    extern __shared__ float xs[];   // [256 d][stride 69]
    const int tid = threadIdx.x;
    const int blk = blockIdx.x;                 // 1024 blocks of 64 pixels
    const int b = blk >> 6, hw0 = (blk & 63) << 6;
    const float* inb = in + ((size_t)b << 20);

    for (int t = tid; t < 256 * 16; t += 256) {
        int d = t >> 4, p4 = t & 15;
        float4 v = *(const float4*)(inb + (size_t)d * HW + hw0 + p4 * 4);
        float* dst = xs + d * 69 + p4 * 4;
        dst[0] = v.x; dst[1] = v.y; dst[2] = v.z; dst[3] = v.w;
    }
    __syncthreads();

    if (tid < 64) {   // sequential-d order -> bit-identical s1
        float s = 0.f;
        for (int d = 0; d < CDIM; ++d) { float v = xs[d * 69 + tid]; s += v * v; }
        s1g[blk * 64 + tid] = s;
    }

    const int d = tid;   // thread owns one channel; iterate the 64 pixels
    for (int i = 0; i < 64; ++i) {
        float x = xs[d * 69 + i];
        __half xh = __float2half_rn(x);
        __half xl = __float2half_rn(x - __half2float(xh));
        size_t row = ((size_t)(blk * 64 + i)) << 9;   // *512
        A_[row + d] = xh;
        A_[row + 256 + d] = xl;
    }
}

// ---------------------------------------------------------------------------
// HMMA GEMM tile: 128 pixels x 128 codes, nt = blk&7 (8 tiles = 1024 codes).
// Inner body: proven R4/R7 code, byte-identical.
// ---------------------------------------------------------------------------
__device__ __forceinline__ void load_chunk(uint32_t sb, const char* Ag, const char* Bg,
                                           int p0, int nt, int kc, int buf, int tid) {
    const uint32_t sA = sb + 4096 + buf * 36864;
    const uint32_t sB = sA + 18432;
    const size_t aoff = (size_t)(kc & 7) * 128;
    const size_t boff = (size_t)kc * 128;
    #pragma unroll
    for (int i = 0; i < 4; ++i) {
        int o = tid + 256 * i;           // 0..1023
        int row = o >> 3, seg = (o & 7) * 16;
        const char* src = Ag + ((size_t)(p0 + row) << 10) + aoff + seg;
        uint32_t dst = sA + row * 144 + seg;
        asm volatile("cp.async.cg.shared.global [%0], [%1], 16;" :: "r"(dst), "l"(src));
    }
    #pragma unroll
    for (int i = 0; i < 4; ++i) {
        int o = tid + 256 * i;
        int row = o >> 3, seg = (o & 7) * 16;
        const char* src = Bg + (size_t)(nt * 128 + row) * 1536 + boff + seg;
        uint32_t dst = sB + row * 144 + seg;
        asm volatile("cp.async.cg.shared.global [%0], [%1], 16;" :: "r"(dst), "l"(src));
    }
}

__global__ void __launch_bounds__(256, 2)
k_gemm(const __half* __restrict__ Ah, const __half* __restrict__ Bh,
       const float* __restrict__ s1g, const float* __restrict__ s2g,
       float* __restrict__ cand_d, int* __restrict__ cand_i) {
    extern __shared__ char sm[];
    uint32_t sb = smem_u32(sm);
    float* rd = (float*)sm;
    int*   ri = (int*)(sm + 1024);
    float* s2s = (float*)(sm + 2048);

    const int tid = threadIdx.x, lane = tid & 31, wid = tid >> 5;
    const int warp_m = wid >> 1, warp_n = wid & 1;
    const int m0 = warp_m * 32, n0 = warp_n * 64;
    const int blk = blockIdx.x, pb = blk >> 3, nt = blk & 7;   // 8 code tiles
    const int p0 = pb * 128;
    const char* Ag = (const char*)Ah;
    const char* Bg = (const char*)Bh;

    if (tid < 128) s2s[tid] = s2g[nt * 128 + tid];

    const int rA = (lane & 7) + ((lane >> 3) & 1) * 8;    // 0..15
    const int cA = (lane >> 4) * 16;                      // 0 or 16 bytes (k8)
    const uint32_t aoff0 = (m0 + 0 + rA) * 144 + cA;
    const uint32_t aoff1 = (m0 + 16 + rA) * 144 + cA;
    const int rB = (lane & 7) + ((lane >> 4) << 3);       // 0..15
    const int cB = ((lane >> 3) & 1) * 16;                // 0 or 16 bytes (k8)
    uint32_t boff[4];
    #pragma unroll
    for (int nb = 0; nb < 4; ++nb) boff[nb] = (n0 + nb * 16 + rB) * 144 + cB;

    float s1v[4];
    #pragma unroll
    for (int s = 0; s < 4; ++s)
        s1v[s] = s1g[p0 + m0 + (s >> 1) * 16 + (lane >> 2) + (s & 1) * 8];

    float c[2][8][4];
    #pragma unroll
    for (int mf = 0; mf < 2; ++mf)
        #pragma unroll
        for (int j = 0; j < 8; ++j)
            #pragma unroll
            for (int q = 0; q < 4; ++q) c[mf][j][q] = 0.f;

    load_chunk(sb, Ag, Bg, p0, nt, 0, 0, tid);
    asm volatile("cp.async.commit_group;" ::: "memory");

    for (int kc = 0; kc < 12; ++kc) {
        const int buf = kc & 1;
        __syncthreads();             // all warps done with buf^1 from kc-1
        if (kc + 1 < 12) {
            load_chunk(sb, Ag, Bg, p0, nt, kc + 1, buf ^ 1, tid);
            asm volatile("cp.async.commit_group;" ::: "memory");
            asm volatile("cp.async.wait_group 1;" ::: "memory");
        } else {
            asm volatile("cp.async.wait_group 0;" ::: "memory");
        }
        __syncthreads();             // chunk `kc` data visible to all

        const uint32_t sA = sb + 4096 + buf * 36864;
        const uint32_t sB = sA + 18432;
        #pragma unroll
        for (int ks = 0; ks < 4; ++ks) {
            uint32_t a0[4], a1[4], bf0[4], bf1[4], bf2[4], bf3[4];
            LDSM4(a0[0], a0[1], a0[2], a0[3], sA + aoff0 + ks * 32);
            LDSM4(a1[0], a1[1], a1[2], a1[3], sA + aoff1 + ks * 32);
            LDSM4(bf0[0], bf0[1], bf0[2], bf0[3], sB + boff[0] + ks * 32);
            LDSM4(bf1[0], bf1[1], bf1[2], bf1[3], sB + boff[1] + ks * 32);
            LDSM4(bf2[0], bf2[1], bf2[2], bf2[3], sB + boff[2] + ks * 32);
            LDSM4(bf3[0], bf3[1], bf3[2], bf3[3], sB + boff[3] + ks * 32);

            MMA16816(c[0][0][0], c[0][0][1], c[0][0][2], c[0][0][3],
                     a0[0], a0[1], a0[2], a0[3], bf0[0], bf0[1]);
            MMA16816(c[0][1][0], c[0][1][1], c[0][1][2], c[0][1][3],
                     a0[0], a0[1], a0[2], a0[3], bf0[2], bf0[3]);
            MMA16816(c[0][2][0], c[0][2][1], c[0][2][2], c[0][2][3],
                     a0[0], a0[1], a0[2], a0[3], bf1[0], bf1[1]);
            MMA16816(c[0][3][0], c[0][3][1], c[0][3][2], c[0][3][3],
                     a0[0], a0[1], a0[2], a0[3], bf1[2], bf1[3]);
            MMA16816(c[0][4][0], c[0][4][1], c[0][4][2], c[0][4][3],
                     a0[0], a0[1], a0[2], a0[3], bf2[0], bf2[1]);
            MMA16816(c[0][5][0], c[0][5][1], c[0][5][2], c[0][5][3],
                     a0[0], a0[1], a0[2], a0[3], bf2[2], bf2[3]);
            MMA16816(c[0][6][0], c[0][6][1], c[0][6][2], c[0][6][3],
                     a0[0], a0[1], a0[2], a0[3], bf3[0], bf3[1]);
            MMA16816(c[0][7][0], c[0][7][1], c[0][7][2], c[0][7][3],
                     a0[0], a0[1], a0[2], a0[3], bf3[2], bf3[3]);

            MMA16816(c[1][0][0], c[1][0][1], c[1][0][2], c[1][0][3],
                     a1[0], a1[1], a1[2], a1[3], bf0[0], bf0[1]);
            MMA16816(c[1][1][0], c[1][1][1], c[1][1][2], c[1][1][3],
                     a1[0], a1[1], a1[2], a1[3], bf0[2], bf0[3]);
            MMA16816(c[1][2][0], c[1][2][1], c[1][2][2], c[1][2][3],
                     a1[0], a1[1], a1[2], a1[3], bf1[0], bf1[1]);
            MMA16816(c[1][3][0], c[1][3][1], c[1][3][2], c[1][3][3],
                     a1[0], a1[1], a1[2], a1[3], bf1[2], bf1[3]);
            MMA16816(c[1][4][0], c[1][4][1], c[1][4][2], c[1][4][3],
                     a1[0], a1[1], a1[2], a1[3], bf2[0], bf2[1]);
            MMA16816(c[1][5][0], c[1][5][1], c[1][5][2], c[1][5][3],
                     a1[0], a1[1], a1[2], a1[3], bf2[2], bf2[3]);
            MMA16816(c[1][6][0], c[1][6][1], c[1][6][2], c[1][6][3],
                     a1[0], a1[1], a1[2], a1[3], bf3[0], bf3[1]);
            MMA16816(c[1][7][0], c[1][7][1], c[1][7][2], c[1][7][3],
                     a1[0], a1[1], a1[2], a1[3], bf3[2], bf3[3]);
        }
    }

    const float SC = 0.001953125f;   // 2^-9
    float bd[4] = {3.4e38f, 3.4e38f, 3.4e38f, 3.4e38f};
    int   bi[4] = {0, 0, 0, 0};
    #pragma unroll
    for (int mf = 0; mf < 2; ++mf) {
        #pragma unroll
        for (int j = 0; j < 8; ++j) {
            const int nl = n0 + j * 8 + ((lane & 3) << 1);
            const float s2a = s2s[nl], s2b = s2s[nl + 1];
            const int sl0 = mf * 2, sl1 = mf * 2 + 1;
            float d0 = (s1v[sl0] + s2a) - c[mf][j][0] * SC;
            float d1 = (s1v[sl0] + s2b) - c[mf][j][1] * SC;
            float d2 = (s1v[sl1] + s2a) - c[mf][j][2] * SC;
            float d3 = (s1v[sl1] + s2b) - c[mf][j][3] * SC;
            if (d0 < bd[sl0]) { bd[sl0] = d0; bi[sl0] = nl; }
            if (d1 < bd[sl0]) { bd[sl0] = d1; bi[sl0] = nl + 1; }
            if (d2 < bd[sl1]) { bd[sl1] = d2; bi[sl1] = nl; }
            if (d3 < bd[sl1]) { bd[sl1] = d3; bi[sl1] = nl + 1; }
        }
    }
    #pragma unroll
    for (int s = 0; s < 4; ++s) {
        #pragma unroll
        for (int off = 1; off <= 2; off <<= 1) {
            float od = __shfl_xor_sync(0xffffffffu, bd[s], off);
            int   oi = __shfl_xor_sync(0xffffffffu, bi[s], off);
            if (od < bd[s] || (od == bd[s] && oi < bi[s])) { bd[s] = od; bi[s] = oi; }
        }
    }
    __syncthreads();
    if ((lane & 3) == 0) {
        #pragma unroll
        for (int s = 0; s < 4; ++s) {
            int row = m0 + (s >> 1) * 16 + (lane >> 2) + (s & 1) * 8;
            rd[row * 2 + warp_n] = bd[s];
            ri[row * 2 + warp_n] = bi[s];
        }
    }
    __syncthreads();
    if (tid < 128) {
        float d0 = rd[tid * 2], d1 = rd[tid * 2 + 1];
        int i0 = ri[tid * 2], i1 = ri[tid * 2 + 1];
        bool t1 = (d1 < d0 || (d1 == d0 && i1 < i0));
        cand_d[(size_t)(p0 + tid) * 8 + nt] = t1 ? d1 : d0;
        cand_i[(size_t)(p0 + tid) * 8 + nt] = nt * 128 + (t1 ? i1 : i0);
    }
}

// ---------------------------------------------------------------------------
// combine 8 candidates per pixel -> final index (+ indices-as-float output)
// ---------------------------------------------------------------------------
__global__ void k_combine(const float* __restrict__ cand_d, const int* __restrict__ cand_i,
                          int* __restrict__ gidx, float* __restrict__ out) {
    int p = blockIdx.x * 256 + threadIdx.x;
    size_t base = (size_t)p * 8;
    float bdv = cand_d[base]; int biv = cand_i[base];
    #pragma unroll
    for (int t = 1; t < 8; ++t) {
        float d = cand_d[base + t]; int i = cand_i[base + t];
        if (d < bdv || (d == bdv && i < biv)) { bdv = d; biv = i; }
    }
    gidx[p] = biv;
    out[IDX_OFF + p] = (float)biv;
}

// ---------------------------------------------------------------------------
// gather quantized output + loss partials   (proven R4 body)
// ---------------------------------------------------------------------------
__global__ void __launch_bounds__(256)
k_out(const float* __restrict__ in, const float* __restrict__ cb,
      const int* __restrict__ gidx, float* __restrict__ out,
      double* __restrict__ partial) {
    __shared__ int idxs[128];
    __shared__ double red[256];
    const int tid = threadIdx.x;
    const int blk = blockIdx.x;
    const int b = blk >> 5, hw0 = (blk & 31) << 7;

    if (tid < 128) idxs[tid] = gidx[(b << 12) + hw0 + tid];
    __syncthreads();

    const float* inb  = in  + ((size_t)b << 20);
    float*       outb = out + ((size_t)b << 20);

    double acc = 0.0;
    for (int t = tid; t < CDIM * 128; t += 256) {
        int d = t >> 7, p = t & 127;
        float q = cb[(size_t)idxs[p] * CDIM + d];
        float x = inb[(size_t)d * HW + hw0 + p];
        outb[(size_t)d * HW + hw0 + p] = q;
        float df = q - x;
        acc += (double)df * (double)df;
    }

    red[tid] = acc;
    __syncthreads();
    #pragma unroll
    for (int s = 128; s > 0; s >>= 1) {
        if (tid < s) red[tid] += red[tid + s];
        __syncthreads();
    }
    if (tid == 0) partial[blk] = red[0];
}

__global__ void k_final(const double* __restrict__ partial, float* __restrict__ out) {
    __shared__ double red[256];
    int tid = threadIdx.x;
    double a = 0.0;
    for (int t = tid; t < NTILES; t += 256) a += partial[t];
    red[tid] = a;
    __syncthreads();
    #pragma unroll
    for (int s = 128; s > 0; s >>= 1) {
        if (tid < s) red[tid] += red[tid + s];
        __syncthreads();
    }
    if (tid == 0) {
        double mse = red[0] / (double)(NPIX * (double)CDIM);
        out[LOSS_OFF] = (float)(1.25 * mse);
    }
}

// ---------------------------------------------------------------------------
extern "C" void kernel_launch(void* const* d_in, const int* in_sizes, int n_in,
                              void* d_out, int out_size) {
    (void)in_sizes; (void)n_in; (void)out_size;
    const float* in = (const float*)d_in[0];
    const float* cb = (const float*)d_in[1];
    float* out = (float*)d_out;

    __half* A_p; __half* B_p;
    float *s1_p, *s2_p, *cd_p; int *ci_p, *idx_p; double* part_p;
    cudaGetSymbolAddress((void**)&A_p,   g_A);
    cudaGetSymbolAddress((void**)&B_p,   g_B);
    cudaGetSymbolAddress((void**)&s1_p,  g_s1);
    cudaGetSymbolAddress((void**)&s2_p,  g_s2);
    cudaGetSymbolAddress((void**)&cd_p,  g_cand_d);
    cudaGetSymbolAddress((void**)&ci_p,  g_cand_i);
    cudaGetSymbolAddress((void**)&idx_p, g_idx);
    cudaGetSymbolAddress((void**)&part_p, g_partial);

    const int smem_a = 256 * 69 * 4;             // 70656 -> 3 CTAs/SM
    const int smem_g = 4096 + 2 * 36864;         // 77824 (proven)
    cudaFuncSetAttribute(k_split_a, cudaFuncAttributeMaxDynamicSharedMemorySize, smem_a);
    cudaFuncSetAttribute(k_gemm,    cudaFuncAttributeMaxDynamicSharedMemorySize, smem_g);

    k_split_b<<<4, 256>>>(cb, B_p, s2_p);
    k_split_a<<<1024, 256, smem_a>>>(in, A_p, s1_p);
    k_gemm<<<4096, 256, smem_g>>>(A_p, B_p, s1_p, s2_p, cd_p, ci_p);
    k_combine<<<256, 256>>>(cd_p, ci_p, idx_p, out);
    k_out<<<NTILES, 256>>>(in, cb, idx_p, out, part_p);
    k_final<<<1, 256>>>(part_p, out);
}